// round 15
// baseline (speedup 1.0000x reference)
#include <cuda_runtime.h>
#include <cuda_fp16.h>
#include <math.h>
#include <stdint.h>

#define Bq   16
#define Sq   256
#define NV   196
#define Dm   768
#define FFd  2048
#define VOC  30522
#define NL   6
#define NHh  8
#define HD   96
#define NTOK (Bq*Sq)        // 4096
#define NMEM (Bq*NV)        // 3136
#define NDEC (Bq*(Sq-1))    // 4080

// -------- scratch (device globals; no allocations allowed) --------
__device__ float  g_x   [NTOK*Dm];
__device__ float  g_o   [NTOK*Dm];
__device__ float  g_dec [NDEC*Dm];
// fp16 activations
__device__ __half g_hx   [NTOK*Dm];
__device__ __half g_hattn[NTOK*Dm];
__device__ __half g_hff  [NTOK*FFd];
__device__ __half g_hdec [NDEC*Dm];
__device__ __half g_hfv  [NMEM*Dm];
__device__ __half g_hqkv [NTOK*3*Dm];
__device__ __half g_hq   [NTOK*Dm];
__device__ __half g_hkv  [NMEM*2*Dm];
// fp16 weights (converted once per launch)
__device__ __half g_h_si[NL*3*Dm*Dm];
__device__ __half g_h_so[NL*Dm*Dm];
__device__ __half g_h_ci[NL*3*Dm*Dm];
__device__ __half g_h_co[NL*Dm*Dm];
__device__ __half g_h_l1[NL*FFd*Dm];
__device__ __half g_h_l2[NL*Dm*FFd];
__device__ __half g_h_fc[(long)VOC*Dm];

// -------- fp32 -> fp16 bulk convert (8 elems/thread) --------
__global__ void f2h_kernel(const float* __restrict__ in, __half* __restrict__ out, int n)
{
    int i = (blockIdx.x * 256 + threadIdx.x) * 8;
    if (i >= n) return;
    float4 v0 = *(const float4*)&in[i];
    float4 v1 = *(const float4*)&in[i + 4];
    uint2 o0, o1;
    __half2 h;
    h = __floats2half2_rn(v0.x, v0.y); o0.x = *(uint32_t*)&h;
    h = __floats2half2_rn(v0.z, v0.w); o0.y = *(uint32_t*)&h;
    h = __floats2half2_rn(v1.x, v1.y); o1.x = *(uint32_t*)&h;
    h = __floats2half2_rn(v1.z, v1.w); o1.y = *(uint32_t*)&h;
    *(uint2*)&out[i]     = o0;
    *(uint2*)&out[i + 4] = o1;
}

// ================== common PTX helpers ==================
__device__ __forceinline__ uint32_t cvta_smem(const void* p) {
    uint32_t a;
    asm("{ .reg .u64 t; cvta.to.shared.u64 t, %1; cvt.u32.u64 %0, t; }"
        : "=r"(a) : "l"(p));
    return a;
}

__device__ __forceinline__ void mma_f16(
    float& c0, float& c1, float& c2, float& c3,
    uint32_t a0, uint32_t a1, uint32_t a2, uint32_t a3,
    uint32_t b0, uint32_t b1)
{
    asm volatile(
        "mma.sync.aligned.m16n8k16.row.col.f32.f16.f16.f32 "
        "{%0,%1,%2,%3}, {%4,%5,%6,%7}, {%8,%9}, {%0,%1,%2,%3};"
        : "+f"(c0), "+f"(c1), "+f"(c2), "+f"(c3)
        : "r"(a0), "r"(a1), "r"(a2), "r"(a3), "r"(b0), "r"(b1));
}

#define LDM_X4(r, addr) \
    asm volatile("ldmatrix.sync.aligned.m8n8.x4.shared.b16 {%0,%1,%2,%3}, [%4];" \
        : "=r"((r)[0]), "=r"((r)[1]), "=r"((r)[2]), "=r"((r)[3]) : "r"(addr))

#define LDM_X4_T(r, addr) \
    asm volatile("ldmatrix.sync.aligned.m8n8.x4.trans.shared.b16 {%0,%1,%2,%3}, [%4];" \
        : "=r"((r)[0]), "=r"((r)[1]), "=r"((r)[2]), "=r"((r)[3]) : "r"(addr))

// ================== FP16 GEMM (R12 mainloop + L2 block swizzle) ==========
#define BM 128
#define BN 128
#define BK 16
#define PADW 12
#define SWZ 8   // column-group width for L2-aware block remap

__global__ __launch_bounds__(256, 2) void mma_gemm(
    const __half* __restrict__ A, const __half* __restrict__ W,
    const float* __restrict__ bias,
    float* __restrict__ Cf, __half* __restrict__ Ch,
    int M, int N, int K, int relu)
{
    __shared__ uint32_t As[2][BM * PADW];
    __shared__ uint32_t Bs[2][BN * PADW];

    int tid  = threadIdx.x;
    int wid  = tid >> 5, lane = tid & 31;
    int g    = lane >> 2;
    int t4   = lane & 3;
    int wm   = (wid >> 2) * 64;
    int wn   = (wid & 3) * 32;

    // L2-aware remap: consecutive CTAs cover SWZ columns x full M
    int nbx = gridDim.x, nby = gridDim.y;
    int bid = blockIdx.y * nbx + blockIdx.x;
    int grp = bid / (SWZ * nby);
    int rem = bid % (SWZ * nby);
    int gx0 = grp * SWZ;
    int gw  = nbx - gx0; if (gw > SWZ) gw = SWZ;
    int bx  = gx0 + rem % gw;
    int by  = rem / gw;
    int m0  = by * BM, n0 = bx * BN;

    int r = tid >> 1, c = tid & 1;
    int ra = m0 + r; if (ra > M - 1) ra = M - 1;
    int rb = n0 + r; if (rb > N - 1) rb = N - 1;
    const __half* Ap = A + (long)ra * K + c * 8;
    const __half* Wp = W + (long)rb * K + c * 8;
    int sidx = r * PADW + c * 4;

    int rA  = lane & 15, khA = lane >> 4;
    uint32_t aoff = (uint32_t)(((wm + rA) * PADW + khA * 4) * 4);
    int qd = lane >> 3, rB = lane & 7;
    uint32_t boff = (uint32_t)(((wn + ((qd >> 1) * 8) + rB) * PADW + (qd & 1) * 4) * 4);

    uint32_t asb[2] = { cvta_smem(As[0]), cvta_smem(As[1]) };
    uint32_t bsb[2] = { cvta_smem(Bs[0]), cvta_smem(Bs[1]) };

    float acc[4][4][4];
    #pragma unroll
    for (int i = 0; i < 4; i++)
        #pragma unroll
        for (int j = 0; j < 4; j++)
            #pragma unroll
            for (int k = 0; k < 4; k++) acc[i][j][k] = 0.f;

    uint4 ra_v, rb_v;
    ra_v = *(const uint4*)(Ap);
    rb_v = *(const uint4*)(Wp);
    *(uint4*)&As[0][sidx] = ra_v;
    *(uint4*)&Bs[0][sidx] = rb_v;
    __syncthreads();

    int nk = K / BK;
    int buf = 0;
    for (int t = 0; t < nk; t++) {
        if (t + 1 < nk) {
            int ko = (t + 1) * BK;
            ra_v = *(const uint4*)(Ap + ko);
            rb_v = *(const uint4*)(Wp + ko);
        }

        uint32_t af[4][4], bf[4][2];
        #pragma unroll
        for (int mt = 0; mt < 4; mt++)
            LDM_X4(af[mt], asb[buf] + aoff + (uint32_t)(mt * 16 * PADW * 4));
        #pragma unroll
        for (int p = 0; p < 2; p++) {
            uint32_t bb[4];
            LDM_X4(bb, bsb[buf] + boff + (uint32_t)(p * 16 * PADW * 4));
            bf[2*p][0]   = bb[0]; bf[2*p][1]   = bb[1];
            bf[2*p+1][0] = bb[2]; bf[2*p+1][1] = bb[3];
        }
        #pragma unroll
        for (int mt = 0; mt < 4; mt++)
            #pragma unroll
            for (int nt = 0; nt < 4; nt++)
                mma_f16(acc[mt][nt][0], acc[mt][nt][1], acc[mt][nt][2], acc[mt][nt][3],
                        af[mt][0], af[mt][1], af[mt][2], af[mt][3],
                        bf[nt][0], bf[nt][1]);

        if (t + 1 < nk) {
            __syncthreads();
            *(uint4*)&As[buf ^ 1][sidx] = ra_v;
            *(uint4*)&Bs[buf ^ 1][sidx] = rb_v;
            __syncthreads();
            buf ^= 1;
        }
    }

    #pragma unroll
    for (int mt = 0; mt < 4; mt++) {
        int row = m0 + wm + mt * 16 + g;
        #pragma unroll
        for (int nt = 0; nt < 4; nt++) {
            int col = n0 + wn + nt * 8 + t4 * 2;
            float v0 = acc[mt][nt][0], v1 = acc[mt][nt][1];
            float v2 = acc[mt][nt][2], v3 = acc[mt][nt][3];
            if (bias) {
                float b0 = (col < N) ? bias[col] : 0.f;
                float b1 = (col + 1 < N) ? bias[col + 1] : 0.f;
                v0 += b0; v1 += b1; v2 += b0; v3 += b1;
            }
            if (relu) {
                v0 = fmaxf(v0, 0.f); v1 = fmaxf(v1, 0.f);
                v2 = fmaxf(v2, 0.f); v3 = fmaxf(v3, 0.f);
            }
            if (Ch) {
                if (row < M && col + 1 < N)
                    *(__half2*)&Ch[(long)row * N + col] = __floats2half2_rn(v0, v1);
                if (row + 8 < M && col + 1 < N)
                    *(__half2*)&Ch[(long)(row + 8) * N + col] = __floats2half2_rn(v2, v3);
            } else {
                if (row < M) {
                    if (col + 1 < N) *(float2*)&Cf[(long)row * N + col] = make_float2(v0, v1);
                    else if (col < N) Cf[(long)row * N + col] = v0;
                }
                if (row + 8 < M) {
                    if (col + 1 < N) *(float2*)&Cf[(long)(row + 8) * N + col] = make_float2(v2, v3);
                    else if (col < N) Cf[(long)(row + 8) * N + col] = v2;
                }
            }
        }
    }
}

// ================== tensor-core flash attention ==================
#define FTQ 64
#define FKC 32
#define LDH 104

__global__ __launch_bounds__(128) void flash_attn(
    const __half* __restrict__ Q, int qs,
    const __half* __restrict__ K, int ks,
    const __half* __restrict__ V, int vs,
    __half* __restrict__ O, int os,
    int Lk, int causal)
{
    __shared__ __half Qs[FTQ][LDH];
    __shared__ __half Ks[FKC][LDH];
    __shared__ __half Vs[FKC][LDH];

    int tid  = threadIdx.x;
    int warp = tid >> 5, lane = tid & 31;
    int g = lane >> 2, t4 = lane & 3;
    int q0 = blockIdx.x * FTQ;
    int h  = blockIdx.y, b = blockIdx.z;

    const __half* Qb = Q + ((long)b * Sq + q0) * qs + h * HD;
    const __half* Kb = K + (long)b * Lk * ks + h * HD;
    const __half* Vb = V + (long)b * Lk * vs + h * HD;

    #pragma unroll
    for (int i = 0; i < 6; i++) {
        int idx = tid + i * 128;
        int row = idx / 12, col = (idx % 12) * 8;
        *(uint4*)&Qs[row][col] = *(const uint4*)&Qb[(long)row * qs + col];
    }
    __syncthreads();

    uint32_t qf[6][4];
    {
        uint32_t qbase = cvta_smem(Qs);
        int row = 16 * warp + (lane & 15);
        int colh = (lane >> 4) * 8;
        #pragma unroll
        for (int kk = 0; kk < 6; kk++)
            LDM_X4(qf[kk], qbase + (uint32_t)((row * LDH + colh + kk * 16) * 2));
    }

    float o[12][4];
    #pragma unroll
    for (int i = 0; i < 12; i++)
        #pragma unroll
        for (int j = 0; j < 4; j++) o[i][j] = 0.f;
    float m0 = -1e30f, m1 = -1e30f, l0 = 0.f, l1 = 0.f;

    uint32_t kbase = cvta_smem(Ks), vbase = cvta_smem(Vs);
    int qd = lane >> 3, rB = lane & 7;
    int vrow_off = ((lane >> 3) & 1) * 8 + (lane & 7);
    int vcol_off = (lane >> 4) * 8;
    const float scale = rsqrtf((float)HD);
    int qrow0 = q0 + 16 * warp + g, qrow1 = qrow0 + 8;

    int nch = (Lk + FKC - 1) / FKC;
    for (int ch = 0; ch < nch; ch++) {
        int k0 = ch * FKC;
        if (causal && k0 > q0 + FTQ - 1) break;
        __syncthreads();
        #pragma unroll
        for (int i = 0; i < 3; i++) {
            int idx = tid + i * 128;
            int row = idx / 12, col = (idx % 12) * 8;
            int kr = k0 + row;
            if (kr < Lk) {
                *(uint4*)&Ks[row][col] = *(const uint4*)&Kb[(long)kr * ks + col];
                *(uint4*)&Vs[row][col] = *(const uint4*)&Vb[(long)kr * vs + col];
            } else {
                uint4 z = make_uint4(0u, 0u, 0u, 0u);
                *(uint4*)&Ks[row][col] = z;
                *(uint4*)&Vs[row][col] = z;
            }
        }
        __syncthreads();

        float s[4][4];
        #pragma unroll
        for (int j = 0; j < 4; j++)
            #pragma unroll
            for (int cc = 0; cc < 4; cc++) s[j][cc] = 0.f;
        #pragma unroll
        for (int kk = 0; kk < 6; kk++) {
            #pragma unroll
            for (int p = 0; p < 2; p++) {
                uint32_t bb[4];
                int krow = 16 * p + (qd >> 1) * 8 + rB;
                LDM_X4(bb, kbase + (uint32_t)((krow * LDH + (qd & 1) * 8 + kk * 16) * 2));
                mma_f16(s[2*p][0], s[2*p][1], s[2*p][2], s[2*p][3],
                        qf[kk][0], qf[kk][1], qf[kk][2], qf[kk][3], bb[0], bb[1]);
                mma_f16(s[2*p+1][0], s[2*p+1][1], s[2*p+1][2], s[2*p+1][3],
                        qf[kk][0], qf[kk][1], qf[kk][2], qf[kk][3], bb[2], bb[3]);
            }
        }
        #pragma unroll
        for (int j = 0; j < 4; j++) {
            int c0 = k0 + 8 * j + 2 * t4, c1 = c0 + 1;
            s[j][0] = (c0 < Lk && (!causal || c0 <= qrow0)) ? s[j][0] * scale : -1e30f;
            s[j][1] = (c1 < Lk && (!causal || c1 <= qrow0)) ? s[j][1] * scale : -1e30f;
            s[j][2] = (c0 < Lk && (!causal || c0 <= qrow1)) ? s[j][2] * scale : -1e30f;
            s[j][3] = (c1 < Lk && (!causal || c1 <= qrow1)) ? s[j][3] * scale : -1e30f;
        }
        float rm0 = -1e30f, rm1 = -1e30f;
        #pragma unroll
        for (int j = 0; j < 4; j++) {
            rm0 = fmaxf(rm0, fmaxf(s[j][0], s[j][1]));
            rm1 = fmaxf(rm1, fmaxf(s[j][2], s[j][3]));
        }
        rm0 = fmaxf(rm0, __shfl_xor_sync(~0u, rm0, 1));
        rm0 = fmaxf(rm0, __shfl_xor_sync(~0u, rm0, 2));
        rm1 = fmaxf(rm1, __shfl_xor_sync(~0u, rm1, 1));
        rm1 = fmaxf(rm1, __shfl_xor_sync(~0u, rm1, 2));
        float mn0 = fmaxf(m0, rm0), mn1 = fmaxf(m1, rm1);
        float f0 = __expf(m0 - mn0), f1 = __expf(m1 - mn1);
        m0 = mn0; m1 = mn1;
        float sum0 = 0.f, sum1 = 0.f;
        uint32_t pa[2][4];
        #pragma unroll
        for (int j = 0; j < 4; j++) {
            float p00 = __expf(s[j][0] - mn0);
            float p01 = __expf(s[j][1] - mn0);
            float p10 = __expf(s[j][2] - mn1);
            float p11 = __expf(s[j][3] - mn1);
            sum0 += p00 + p01; sum1 += p10 + p11;
            __half2 hh = __floats2half2_rn(p00, p01);
            pa[j >> 1][(j & 1) * 2 + 0] = *(uint32_t*)&hh;
            hh = __floats2half2_rn(p10, p11);
            pa[j >> 1][(j & 1) * 2 + 1] = *(uint32_t*)&hh;
        }
        l0 = l0 * f0 + sum0;
        l1 = l1 * f1 + sum1;
        #pragma unroll
        for (int nt = 0; nt < 12; nt++) {
            o[nt][0] *= f0; o[nt][1] *= f0;
            o[nt][2] *= f1; o[nt][3] *= f1;
        }
        #pragma unroll
        for (int st = 0; st < 2; st++) {
            #pragma unroll
            for (int np = 0; np < 6; np++) {
                uint32_t bb[4];
                int krow = st * 16 + vrow_off;
                int ncol = np * 16 + vcol_off;
                LDM_X4_T(bb, vbase + (uint32_t)((krow * LDH + ncol) * 2));
                mma_f16(o[2*np][0], o[2*np][1], o[2*np][2], o[2*np][3],
                        pa[st][0], pa[st][1], pa[st][2], pa[st][3], bb[0], bb[1]);
                mma_f16(o[2*np+1][0], o[2*np+1][1], o[2*np+1][2], o[2*np+1][3],
                        pa[st][0], pa[st][1], pa[st][2], pa[st][3], bb[2], bb[3]);
            }
        }
    }

    l0 += __shfl_xor_sync(~0u, l0, 1);
    l0 += __shfl_xor_sync(~0u, l0, 2);
    l1 += __shfl_xor_sync(~0u, l1, 1);
    l1 += __shfl_xor_sync(~0u, l1, 2);
    float inv0 = 1.f / l0, inv1 = 1.f / l1;
    __half* Ob = O + ((long)b * Sq + q0 + 16 * warp) * os + h * HD;
    #pragma unroll
    for (int nt = 0; nt < 12; nt++) {
        int col = 8 * nt + 2 * t4;
        *(__half2*)&Ob[(long)g * os + col] =
            __floats2half2_rn(o[nt][0] * inv0, o[nt][1] * inv0);
        *(__half2*)&Ob[(long)(g + 8) * os + col] =
            __floats2half2_rn(o[nt][2] * inv1, o[nt][3] * inv1);
    }
}

// -------- residual add + layernorm (in-place on X, dual write fp16) ------
__global__ __launch_bounds__(256) void add_ln_kernel(
    float* __restrict__ X, const float* __restrict__ Y,
    const float* __restrict__ w, const float* __restrict__ b,
    __half* __restrict__ HX)
{
    long t = blockIdx.x;
    int tid = threadIdx.x;
    __shared__ float red[256];
    float vals[3];
    float s = 0.f;
    #pragma unroll
    for (int i = 0; i < 3; i++) {
        int d = tid + i * 256;
        float v = X[t * Dm + d] + Y[t * Dm + d];
        vals[i] = v;
        s += v;
    }
    red[tid] = s; __syncthreads();
    for (int st = 128; st > 0; st >>= 1) {
        if (tid < st) red[tid] += red[tid + st];
        __syncthreads();
    }
    float mean = red[0] * (1.f / Dm);
    __syncthreads();
    float s2 = 0.f;
    #pragma unroll
    for (int i = 0; i < 3; i++) { float dv = vals[i] - mean; s2 += dv * dv; }
    red[tid] = s2; __syncthreads();
    for (int st = 128; st > 0; st >>= 1) {
        if (tid < st) red[tid] += red[tid + st];
        __syncthreads();
    }
    float rstd = rsqrtf(red[0] * (1.f / Dm) + 1e-5f);
    #pragma unroll
    for (int i = 0; i < 3; i++) {
        int d = tid + i * 256;
        float o = (vals[i] - mean) * rstd * w[d] + b[d];
        X[t * Dm + d]  = o;
        HX[t * Dm + d] = __float2half_rn(o);
    }
}

// -------- x = target_embed + sinusoid PE (dual write) --------
__global__ void pe_kernel(const float* __restrict__ te,
                          float* __restrict__ x, __half* __restrict__ hx)
{
    int idx = blockIdx.x * 256 + threadIdx.x;
    if (idx >= NTOK * Dm) return;
    int d = idx % Dm;
    int tok = idx / Dm;
    int s = tok % Sq;
    int j = d >> 1;
    float div = expf(-(float)(2 * j) * (logf(10000.f) / (float)Dm));
    float ang = (float)s * div;
    float p = (d & 1) ? cosf(ang) : sinf(ang);
    float o = te[idx] + p;
    x[idx]  = o;
    hx[idx] = __float2half_rn(o);
}

// -------- gather dec = x[:, :S-1, :] (dual write) --------
__global__ void dec_gather(const float* __restrict__ x,
                           float* __restrict__ dec, __half* __restrict__ hdec)
{
    int idx = blockIdx.x * 256 + threadIdx.x;
    if (idx >= NDEC * Dm) return;
    int d = idx % Dm;
    int rr = idx / Dm;
    int b = rr / (Sq - 1);
    int s = rr % (Sq - 1);
    float v = x[((long)(b * Sq + s)) * Dm + d];
    dec[idx]  = v;
    hdec[idx] = __float2half_rn(v);
}

// -------- F_t = softmax(dec, axis=-1) --------
__global__ __launch_bounds__(256) void ft_softmax(
    const float* __restrict__ dec, float* __restrict__ out)
{
    long rr = blockIdx.x;
    int tid = threadIdx.x;
    __shared__ float red[256];
    float v[3];
    float mx = -1e30f;
    #pragma unroll
    for (int i = 0; i < 3; i++) {
        v[i] = dec[rr * Dm + tid + i * 256];
        mx = fmaxf(mx, v[i]);
    }
    red[tid] = mx; __syncthreads();
    for (int st = 128; st > 0; st >>= 1) {
        if (tid < st) red[tid] = fmaxf(red[tid], red[tid + st]);
        __syncthreads();
    }
    float m = red[0]; __syncthreads();
    float s = 0.f;
    #pragma unroll
    for (int i = 0; i < 3; i++) { v[i] = __expf(v[i] - m); s += v[i]; }
    red[tid] = s; __syncthreads();
    for (int st = 128; st > 0; st >>= 1) {
        if (tid < st) red[tid] += red[tid + st];
        __syncthreads();
    }
    float inv = 1.f / red[0];
    #pragma unroll
    for (int i = 0; i < 3; i++)
        out[rr * Dm + tid + i * 256] = v[i] * inv;
}

static inline dim3 gemm_grid(int M, int N) {
    return dim3((N + BN - 1) / BN, (M + BM - 1) / BM);
}
static inline int conv_grid(long n) { return (int)((n / 8 + 255) / 256); }

extern "C" void kernel_launch(void* const* d_in, const int* in_sizes, int n_in,
                              void* d_out, int out_size)
{
    const float* fv          = (const float*)d_in[0];
    const float* te          = (const float*)d_in[1];
    const float* self_in_w   = (const float*)d_in[2];
    const float* self_in_b   = (const float*)d_in[3];
    const float* self_out_w  = (const float*)d_in[4];
    const float* self_out_b  = (const float*)d_in[5];
    const float* cross_in_w  = (const float*)d_in[6];
    const float* cross_in_b  = (const float*)d_in[7];
    const float* cross_out_w = (const float*)d_in[8];
    const float* cross_out_b = (const float*)d_in[9];
    const float* lin1_w      = (const float*)d_in[10];
    const float* lin1_b      = (const float*)d_in[11];
    const float* lin2_w      = (const float*)d_in[12];
    const float* lin2_b      = (const float*)d_in[13];
    const float* ln_w        = (const float*)d_in[14];
    const float* ln_b        = (const float*)d_in[15];
    const float* fc_out_w    = (const float*)d_in[16];

    float* out    = (float*)d_out;
    float* logits = out;
    float* ft     = out + (long)NDEC * VOC;

    float *px, *po, *pdec;
    __half *hx, *hattn, *hff, *hdec, *hfv, *hqkv, *hq, *hkv;
    __half *hsi, *hso, *hci, *hco, *hl1, *hl2, *hfc;
    cudaGetSymbolAddress((void**)&px,    g_x);
    cudaGetSymbolAddress((void**)&po,    g_o);
    cudaGetSymbolAddress((void**)&pdec,  g_dec);
    cudaGetSymbolAddress((void**)&hx,    g_hx);
    cudaGetSymbolAddress((void**)&hattn, g_hattn);
    cudaGetSymbolAddress((void**)&hff,   g_hff);
    cudaGetSymbolAddress((void**)&hdec,  g_hdec);
    cudaGetSymbolAddress((void**)&hfv,   g_hfv);
    cudaGetSymbolAddress((void**)&hqkv,  g_hqkv);
    cudaGetSymbolAddress((void**)&hq,    g_hq);
    cudaGetSymbolAddress((void**)&hkv,   g_hkv);
    cudaGetSymbolAddress((void**)&hsi,   g_h_si);
    cudaGetSymbolAddress((void**)&hso,   g_h_so);
    cudaGetSymbolAddress((void**)&hci,   g_h_ci);
    cudaGetSymbolAddress((void**)&hco,   g_h_co);
    cudaGetSymbolAddress((void**)&hl1,   g_h_l1);
    cudaGetSymbolAddress((void**)&hl2,   g_h_l2);
    cudaGetSymbolAddress((void**)&hfc,   g_h_fc);

    f2h_kernel<<<conv_grid((long)NL*3*Dm*Dm), 256>>>(self_in_w,  hsi, NL*3*Dm*Dm);
    f2h_kernel<<<conv_grid((long)NL*Dm*Dm),   256>>>(self_out_w, hso, NL*Dm*Dm);
    f2h_kernel<<<conv_grid((long)NL*3*Dm*Dm), 256>>>(cross_in_w, hci, NL*3*Dm*Dm);
    f2h_kernel<<<conv_grid((long)NL*Dm*Dm),   256>>>(cross_out_w,hco, NL*Dm*Dm);
    f2h_kernel<<<conv_grid((long)NL*FFd*Dm),  256>>>(lin1_w,     hl1, NL*FFd*Dm);
    f2h_kernel<<<conv_grid((long)NL*Dm*FFd),  256>>>(lin2_w,     hl2, NL*Dm*FFd);
    f2h_kernel<<<conv_grid((long)VOC*Dm),     256>>>(fc_out_w,   hfc, (int)((long)VOC*Dm));
    f2h_kernel<<<conv_grid((long)NMEM*Dm),    256>>>(fv,         hfv, NMEM*Dm);

    pe_kernel<<<(NTOK * Dm + 255) / 256, 256>>>(te, px, hx);

    dim3 agrid(Sq / FTQ, NHh, Bq);

    for (int l = 0; l < NL; l++) {
        const __half* siw = hsi + (long)l * 3 * Dm * Dm;
        const __half* sow = hso + (long)l * Dm * Dm;
        const __half* ciw = hci + (long)l * 3 * Dm * Dm;
        const __half* cow = hco + (long)l * Dm * Dm;
        const __half* l1w = hl1 + (long)l * FFd * Dm;
        const __half* l2w = hl2 + (long)l * Dm * FFd;
        const float* sib = self_in_b  + (long)l * 3 * Dm;
        const float* sob = self_out_b + (long)l * Dm;
        const float* cib = cross_in_b  + (long)l * 3 * Dm;
        const float* cob = cross_out_b + (long)l * Dm;
        const float* l1b = lin1_b + (long)l * FFd;
        const float* l2b = lin2_b + (long)l * Dm;
        const float* lw  = ln_w + (long)l * 3 * Dm;
        const float* lb  = ln_b + (long)l * 3 * Dm;

        // ---- self attention ----
        mma_gemm<<<gemm_grid(NTOK, 3 * Dm), 256>>>(hx, siw, sib, nullptr, hqkv,
                                                   NTOK, 3 * Dm, Dm, 0);
        flash_attn<<<agrid, 128>>>(hqkv, 3 * Dm,
                                   hqkv + Dm, 3 * Dm,
                                   hqkv + 2 * Dm, 3 * Dm,
                                   hattn, Dm, Sq, 1);
        mma_gemm<<<gemm_grid(NTOK, Dm), 256>>>(hattn, sow, sob, po, nullptr,
                                               NTOK, Dm, Dm, 0);
        add_ln_kernel<<<NTOK, 256>>>(px, po, lw, lb, hx);

        // ---- cross attention ----
        mma_gemm<<<gemm_grid(NTOK, Dm), 256>>>(hx, ciw, cib, nullptr, hq,
                                               NTOK, Dm, Dm, 0);
        mma_gemm<<<gemm_grid(NMEM, 2 * Dm), 256>>>(hfv, ciw + (long)Dm * Dm,
                                                   cib + Dm, nullptr, hkv,
                                                   NMEM, 2 * Dm, Dm, 0);
        flash_attn<<<agrid, 128>>>(hq, Dm,
                                   hkv, 2 * Dm,
                                   hkv + Dm, 2 * Dm,
                                   hattn, Dm, NV, 0);
        mma_gemm<<<gemm_grid(NTOK, Dm), 256>>>(hattn, cow, cob, po, nullptr,
                                               NTOK, Dm, Dm, 0);
        add_ln_kernel<<<NTOK, 256>>>(px, po, lw + Dm, lb + Dm, hx);

        // ---- FFN ----
        mma_gemm<<<gemm_grid(NTOK, FFd), 256>>>(hx, l1w, l1b, nullptr, hff,
                                                NTOK, FFd, Dm, 1);
        mma_gemm<<<gemm_grid(NTOK, Dm), 256>>>(hff, l2w, l2b, po, nullptr,
                                               NTOK, Dm, FFd, 0);
        add_ln_kernel<<<NTOK, 256>>>(px, po, lw + 2 * Dm, lb + 2 * Dm, hx);
    }

    dec_gather<<<(NDEC * Dm + 255) / 256, 256>>>(px, pdec, hdec);
    mma_gemm<<<gemm_grid(NDEC, VOC), 256>>>(hdec, hfc, nullptr, logits, nullptr,
                                            NDEC, VOC, Dm, 0);
    ft_softmax<<<NDEC, 256>>>(pdec, ft);
}

// round 16
// speedup vs baseline: 1.0077x; 1.0077x over previous
#include <cuda_runtime.h>
#include <cuda_fp16.h>
#include <math.h>
#include <stdint.h>

#define Bq   16
#define Sq   256
#define NV   196
#define Dm   768
#define FFd  2048
#define VOC  30522
#define NL   6
#define NHh  8
#define HD   96
#define NTOK (Bq*Sq)        // 4096
#define NMEM (Bq*NV)        // 3136
#define NDEC (Bq*(Sq-1))    // 4080

// -------- scratch (device globals; no allocations allowed) --------
__device__ float  g_x   [NTOK*Dm];
__device__ float  g_o   [NTOK*Dm];
// fp16 activations
__device__ __half g_hx   [NTOK*Dm];
__device__ __half g_hattn[NTOK*Dm];
__device__ __half g_hff  [NTOK*FFd];
__device__ __half g_hdec [NDEC*Dm];
__device__ __half g_hfv  [NMEM*Dm];
__device__ __half g_hqkv [NTOK*3*Dm];
__device__ __half g_hq   [NTOK*Dm];
__device__ __half g_hkv6 [(long)NL*NMEM*2*Dm];   // all-layer cross-KV
// fp16 weights (converted once per launch)
__device__ __half g_h_si[NL*3*Dm*Dm];
__device__ __half g_h_so[NL*Dm*Dm];
__device__ __half g_h_ci[NL*3*Dm*Dm];
__device__ __half g_h_co[NL*Dm*Dm];
__device__ __half g_h_l1[NL*FFd*Dm];
__device__ __half g_h_l2[NL*Dm*FFd];
__device__ __half g_h_fc[(long)VOC*Dm];

// -------- fp32 -> fp16 bulk convert (8 elems/thread) --------
__global__ void f2h_kernel(const float* __restrict__ in, __half* __restrict__ out, int n)
{
    int i = (blockIdx.x * 256 + threadIdx.x) * 8;
    if (i >= n) return;
    float4 v0 = *(const float4*)&in[i];
    float4 v1 = *(const float4*)&in[i + 4];
    uint2 o0, o1;
    __half2 h;
    h = __floats2half2_rn(v0.x, v0.y); o0.x = *(uint32_t*)&h;
    h = __floats2half2_rn(v0.z, v0.w); o0.y = *(uint32_t*)&h;
    h = __floats2half2_rn(v1.x, v1.y); o1.x = *(uint32_t*)&h;
    h = __floats2half2_rn(v1.z, v1.w); o1.y = *(uint32_t*)&h;
    *(uint2*)&out[i]     = o0;
    *(uint2*)&out[i + 4] = o1;
}

// ================== common PTX helpers ==================
__device__ __forceinline__ uint32_t cvta_smem(const void* p) {
    uint32_t a;
    asm("{ .reg .u64 t; cvta.to.shared.u64 t, %1; cvt.u32.u64 %0, t; }"
        : "=r"(a) : "l"(p));
    return a;
}

__device__ __forceinline__ void mma_f16(
    float& c0, float& c1, float& c2, float& c3,
    uint32_t a0, uint32_t a1, uint32_t a2, uint32_t a3,
    uint32_t b0, uint32_t b1)
{
    asm volatile(
        "mma.sync.aligned.m16n8k16.row.col.f32.f16.f16.f32 "
        "{%0,%1,%2,%3}, {%4,%5,%6,%7}, {%8,%9}, {%0,%1,%2,%3};"
        : "+f"(c0), "+f"(c1), "+f"(c2), "+f"(c3)
        : "r"(a0), "r"(a1), "r"(a2), "r"(a3), "r"(b0), "r"(b1));
}

#define LDM_X4(r, addr) \
    asm volatile("ldmatrix.sync.aligned.m8n8.x4.shared.b16 {%0,%1,%2,%3}, [%4];" \
        : "=r"((r)[0]), "=r"((r)[1]), "=r"((r)[2]), "=r"((r)[3]) : "r"(addr))

#define LDM_X4_T(r, addr) \
    asm volatile("ldmatrix.sync.aligned.m8n8.x4.trans.shared.b16 {%0,%1,%2,%3}, [%4];" \
        : "=r"((r)[0]), "=r"((r)[1]), "=r"((r)[2]), "=r"((r)[3]) : "r"(addr))

// ================== FP16 GEMM (R12 mainloop, batched via blockIdx.z) ======
#define BM 128
#define BN 128
#define BK 16
#define PADW 12

__global__ __launch_bounds__(256, 2) void mma_gemm(
    const __half* __restrict__ A, const __half* __restrict__ W,
    const float* __restrict__ bias,
    float* __restrict__ Cf, __half* __restrict__ Ch,
    int M, int N, int K, int relu,
    long sA, long sW, long sB, long sC)
{
    __shared__ uint32_t As[2][BM * PADW];
    __shared__ uint32_t Bs[2][BN * PADW];

    int z = blockIdx.z;
    A += (long)z * sA;
    W += (long)z * sW;
    if (bias) bias += (long)z * sB;
    if (Ch) Ch += (long)z * sC;
    if (Cf) Cf += (long)z * sC;

    int tid  = threadIdx.x;
    int wid  = tid >> 5, lane = tid & 31;
    int g    = lane >> 2;
    int t4   = lane & 3;
    int wm   = (wid >> 2) * 64;
    int wn   = (wid & 3) * 32;
    int m0   = blockIdx.y * BM, n0 = blockIdx.x * BN;

    int r = tid >> 1, c = tid & 1;
    int ra = m0 + r; if (ra > M - 1) ra = M - 1;
    int rb = n0 + r; if (rb > N - 1) rb = N - 1;
    const __half* Ap = A + (long)ra * K + c * 8;
    const __half* Wp = W + (long)rb * K + c * 8;
    int sidx = r * PADW + c * 4;

    int rA  = lane & 15, khA = lane >> 4;
    uint32_t aoff = (uint32_t)(((wm + rA) * PADW + khA * 4) * 4);
    int qd = lane >> 3, rB = lane & 7;
    uint32_t boff = (uint32_t)(((wn + ((qd >> 1) * 8) + rB) * PADW + (qd & 1) * 4) * 4);

    uint32_t asb[2] = { cvta_smem(As[0]), cvta_smem(As[1]) };
    uint32_t bsb[2] = { cvta_smem(Bs[0]), cvta_smem(Bs[1]) };

    float acc[4][4][4];
    #pragma unroll
    for (int i = 0; i < 4; i++)
        #pragma unroll
        for (int j = 0; j < 4; j++)
            #pragma unroll
            for (int k = 0; k < 4; k++) acc[i][j][k] = 0.f;

    uint4 ra_v, rb_v;
    ra_v = *(const uint4*)(Ap);
    rb_v = *(const uint4*)(Wp);
    *(uint4*)&As[0][sidx] = ra_v;
    *(uint4*)&Bs[0][sidx] = rb_v;
    __syncthreads();

    int nk = K / BK;
    int buf = 0;
    for (int t = 0; t < nk; t++) {
        if (t + 1 < nk) {
            int ko = (t + 1) * BK;
            ra_v = *(const uint4*)(Ap + ko);
            rb_v = *(const uint4*)(Wp + ko);
        }

        uint32_t af[4][4], bf[4][2];
        #pragma unroll
        for (int mt = 0; mt < 4; mt++)
            LDM_X4(af[mt], asb[buf] + aoff + (uint32_t)(mt * 16 * PADW * 4));
        #pragma unroll
        for (int p = 0; p < 2; p++) {
            uint32_t bb[4];
            LDM_X4(bb, bsb[buf] + boff + (uint32_t)(p * 16 * PADW * 4));
            bf[2*p][0]   = bb[0]; bf[2*p][1]   = bb[1];
            bf[2*p+1][0] = bb[2]; bf[2*p+1][1] = bb[3];
        }
        #pragma unroll
        for (int mt = 0; mt < 4; mt++)
            #pragma unroll
            for (int nt = 0; nt < 4; nt++)
                mma_f16(acc[mt][nt][0], acc[mt][nt][1], acc[mt][nt][2], acc[mt][nt][3],
                        af[mt][0], af[mt][1], af[mt][2], af[mt][3],
                        bf[nt][0], bf[nt][1]);

        if (t + 1 < nk) {
            __syncthreads();
            *(uint4*)&As[buf ^ 1][sidx] = ra_v;
            *(uint4*)&Bs[buf ^ 1][sidx] = rb_v;
            __syncthreads();
            buf ^= 1;
        }
    }

    #pragma unroll
    for (int mt = 0; mt < 4; mt++) {
        int row = m0 + wm + mt * 16 + g;
        #pragma unroll
        for (int nt = 0; nt < 4; nt++) {
            int col = n0 + wn + nt * 8 + t4 * 2;
            float v0 = acc[mt][nt][0], v1 = acc[mt][nt][1];
            float v2 = acc[mt][nt][2], v3 = acc[mt][nt][3];
            if (bias) {
                float b0 = (col < N) ? bias[col] : 0.f;
                float b1 = (col + 1 < N) ? bias[col + 1] : 0.f;
                v0 += b0; v1 += b1; v2 += b0; v3 += b1;
            }
            if (relu) {
                v0 = fmaxf(v0, 0.f); v1 = fmaxf(v1, 0.f);
                v2 = fmaxf(v2, 0.f); v3 = fmaxf(v3, 0.f);
            }
            if (Ch) {
                if (row < M && col + 1 < N)
                    *(__half2*)&Ch[(long)row * N + col] = __floats2half2_rn(v0, v1);
                if (row + 8 < M && col + 1 < N)
                    *(__half2*)&Ch[(long)(row + 8) * N + col] = __floats2half2_rn(v2, v3);
            } else {
                if (row < M) {
                    if (col + 1 < N) *(float2*)&Cf[(long)row * N + col] = make_float2(v0, v1);
                    else if (col < N) Cf[(long)row * N + col] = v0;
                }
                if (row + 8 < M) {
                    if (col + 1 < N) *(float2*)&Cf[(long)(row + 8) * N + col] = make_float2(v2, v3);
                    else if (col < N) Cf[(long)(row + 8) * N + col] = v2;
                }
            }
        }
    }
}

// ================== tensor-core flash attention ==================
#define FTQ 64
#define FKC 32
#define LDH 104

__global__ __launch_bounds__(128) void flash_attn(
    const __half* __restrict__ Q, int qs,
    const __half* __restrict__ K, int ks,
    const __half* __restrict__ V, int vs,
    __half* __restrict__ O, int os,
    int Lk, int causal)
{
    __shared__ __half Qs[FTQ][LDH];
    __shared__ __half Ks[FKC][LDH];
    __shared__ __half Vs[FKC][LDH];

    int tid  = threadIdx.x;
    int warp = tid >> 5, lane = tid & 31;
    int g = lane >> 2, t4 = lane & 3;
    int q0 = blockIdx.x * FTQ;
    int h  = blockIdx.y, b = blockIdx.z;

    const __half* Qb = Q + ((long)b * Sq + q0) * qs + h * HD;
    const __half* Kb = K + (long)b * Lk * ks + h * HD;
    const __half* Vb = V + (long)b * Lk * vs + h * HD;

    #pragma unroll
    for (int i = 0; i < 6; i++) {
        int idx = tid + i * 128;
        int row = idx / 12, col = (idx % 12) * 8;
        *(uint4*)&Qs[row][col] = *(const uint4*)&Qb[(long)row * qs + col];
    }
    __syncthreads();

    uint32_t qf[6][4];
    {
        uint32_t qbase = cvta_smem(Qs);
        int row = 16 * warp + (lane & 15);
        int colh = (lane >> 4) * 8;
        #pragma unroll
        for (int kk = 0; kk < 6; kk++)
            LDM_X4(qf[kk], qbase + (uint32_t)((row * LDH + colh + kk * 16) * 2));
    }

    float o[12][4];
    #pragma unroll
    for (int i = 0; i < 12; i++)
        #pragma unroll
        for (int j = 0; j < 4; j++) o[i][j] = 0.f;
    float m0 = -1e30f, m1 = -1e30f, l0 = 0.f, l1 = 0.f;

    uint32_t kbase = cvta_smem(Ks), vbase = cvta_smem(Vs);
    int qd = lane >> 3, rB = lane & 7;
    int vrow_off = ((lane >> 3) & 1) * 8 + (lane & 7);
    int vcol_off = (lane >> 4) * 8;
    const float scale = rsqrtf((float)HD);
    int qrow0 = q0 + 16 * warp + g, qrow1 = qrow0 + 8;

    int nch = (Lk + FKC - 1) / FKC;
    for (int ch = 0; ch < nch; ch++) {
        int k0 = ch * FKC;
        if (causal && k0 > q0 + FTQ - 1) break;
        __syncthreads();
        #pragma unroll
        for (int i = 0; i < 3; i++) {
            int idx = tid + i * 128;
            int row = idx / 12, col = (idx % 12) * 8;
            int kr = k0 + row;
            if (kr < Lk) {
                *(uint4*)&Ks[row][col] = *(const uint4*)&Kb[(long)kr * ks + col];
                *(uint4*)&Vs[row][col] = *(const uint4*)&Vb[(long)kr * vs + col];
            } else {
                uint4 z = make_uint4(0u, 0u, 0u, 0u);
                *(uint4*)&Ks[row][col] = z;
                *(uint4*)&Vs[row][col] = z;
            }
        }
        __syncthreads();

        float s[4][4];
        #pragma unroll
        for (int j = 0; j < 4; j++)
            #pragma unroll
            for (int cc = 0; cc < 4; cc++) s[j][cc] = 0.f;
        #pragma unroll
        for (int kk = 0; kk < 6; kk++) {
            #pragma unroll
            for (int p = 0; p < 2; p++) {
                uint32_t bb[4];
                int krow = 16 * p + (qd >> 1) * 8 + rB;
                LDM_X4(bb, kbase + (uint32_t)((krow * LDH + (qd & 1) * 8 + kk * 16) * 2));
                mma_f16(s[2*p][0], s[2*p][1], s[2*p][2], s[2*p][3],
                        qf[kk][0], qf[kk][1], qf[kk][2], qf[kk][3], bb[0], bb[1]);
                mma_f16(s[2*p+1][0], s[2*p+1][1], s[2*p+1][2], s[2*p+1][3],
                        qf[kk][0], qf[kk][1], qf[kk][2], qf[kk][3], bb[2], bb[3]);
            }
        }
        #pragma unroll
        for (int j = 0; j < 4; j++) {
            int c0 = k0 + 8 * j + 2 * t4, c1 = c0 + 1;
            s[j][0] = (c0 < Lk && (!causal || c0 <= qrow0)) ? s[j][0] * scale : -1e30f;
            s[j][1] = (c1 < Lk && (!causal || c1 <= qrow0)) ? s[j][1] * scale : -1e30f;
            s[j][2] = (c0 < Lk && (!causal || c0 <= qrow1)) ? s[j][2] * scale : -1e30f;
            s[j][3] = (c1 < Lk && (!causal || c1 <= qrow1)) ? s[j][3] * scale : -1e30f;
        }
        float rm0 = -1e30f, rm1 = -1e30f;
        #pragma unroll
        for (int j = 0; j < 4; j++) {
            rm0 = fmaxf(rm0, fmaxf(s[j][0], s[j][1]));
            rm1 = fmaxf(rm1, fmaxf(s[j][2], s[j][3]));
        }
        rm0 = fmaxf(rm0, __shfl_xor_sync(~0u, rm0, 1));
        rm0 = fmaxf(rm0, __shfl_xor_sync(~0u, rm0, 2));
        rm1 = fmaxf(rm1, __shfl_xor_sync(~0u, rm1, 1));
        rm1 = fmaxf(rm1, __shfl_xor_sync(~0u, rm1, 2));
        float mn0 = fmaxf(m0, rm0), mn1 = fmaxf(m1, rm1);
        float f0 = __expf(m0 - mn0), f1 = __expf(m1 - mn1);
        m0 = mn0; m1 = mn1;
        float sum0 = 0.f, sum1 = 0.f;
        uint32_t pa[2][4];
        #pragma unroll
        for (int j = 0; j < 4; j++) {
            float p00 = __expf(s[j][0] - mn0);
            float p01 = __expf(s[j][1] - mn0);
            float p10 = __expf(s[j][2] - mn1);
            float p11 = __expf(s[j][3] - mn1);
            sum0 += p00 + p01; sum1 += p10 + p11;
            __half2 hh = __floats2half2_rn(p00, p01);
            pa[j >> 1][(j & 1) * 2 + 0] = *(uint32_t*)&hh;
            hh = __floats2half2_rn(p10, p11);
            pa[j >> 1][(j & 1) * 2 + 1] = *(uint32_t*)&hh;
        }
        l0 = l0 * f0 + sum0;
        l1 = l1 * f1 + sum1;
        #pragma unroll
        for (int nt = 0; nt < 12; nt++) {
            o[nt][0] *= f0; o[nt][1] *= f0;
            o[nt][2] *= f1; o[nt][3] *= f1;
        }
        #pragma unroll
        for (int st = 0; st < 2; st++) {
            #pragma unroll
            for (int np = 0; np < 6; np++) {
                uint32_t bb[4];
                int krow = st * 16 + vrow_off;
                int ncol = np * 16 + vcol_off;
                LDM_X4_T(bb, vbase + (uint32_t)((krow * LDH + ncol) * 2));
                mma_f16(o[2*np][0], o[2*np][1], o[2*np][2], o[2*np][3],
                        pa[st][0], pa[st][1], pa[st][2], pa[st][3], bb[0], bb[1]);
                mma_f16(o[2*np+1][0], o[2*np+1][1], o[2*np+1][2], o[2*np+1][3],
                        pa[st][0], pa[st][1], pa[st][2], pa[st][3], bb[2], bb[3]);
            }
        }
    }

    l0 += __shfl_xor_sync(~0u, l0, 1);
    l0 += __shfl_xor_sync(~0u, l0, 2);
    l1 += __shfl_xor_sync(~0u, l1, 1);
    l1 += __shfl_xor_sync(~0u, l1, 2);
    float inv0 = 1.f / l0, inv1 = 1.f / l1;
    __half* Ob = O + ((long)b * Sq + q0 + 16 * warp) * os + h * HD;
    #pragma unroll
    for (int nt = 0; nt < 12; nt++) {
        int col = 8 * nt + 2 * t4;
        *(__half2*)&Ob[(long)g * os + col] =
            __floats2half2_rn(o[nt][0] * inv0, o[nt][1] * inv0);
        *(__half2*)&Ob[(long)(g + 8) * os + col] =
            __floats2half2_rn(o[nt][2] * inv1, o[nt][3] * inv1);
    }
}

// -------- residual add + layernorm (in-place on X, dual write fp16) ------
__global__ __launch_bounds__(256) void add_ln_kernel(
    float* __restrict__ X, const float* __restrict__ Y,
    const float* __restrict__ w, const float* __restrict__ b,
    __half* __restrict__ HX)
{
    long t = blockIdx.x;
    int tid = threadIdx.x;
    __shared__ float red[256];
    float vals[3];
    float s = 0.f;
    #pragma unroll
    for (int i = 0; i < 3; i++) {
        int d = tid + i * 256;
        float v = X[t * Dm + d] + Y[t * Dm + d];
        vals[i] = v;
        s += v;
    }
    red[tid] = s; __syncthreads();
    for (int st = 128; st > 0; st >>= 1) {
        if (tid < st) red[tid] += red[tid + st];
        __syncthreads();
    }
    float mean = red[0] * (1.f / Dm);
    __syncthreads();
    float s2 = 0.f;
    #pragma unroll
    for (int i = 0; i < 3; i++) { float dv = vals[i] - mean; s2 += dv * dv; }
    red[tid] = s2; __syncthreads();
    for (int st = 128; st > 0; st >>= 1) {
        if (tid < st) red[tid] += red[tid + st];
        __syncthreads();
    }
    float rstd = rsqrtf(red[0] * (1.f / Dm) + 1e-5f);
    #pragma unroll
    for (int i = 0; i < 3; i++) {
        int d = tid + i * 256;
        float o = (vals[i] - mean) * rstd * w[d] + b[d];
        X[t * Dm + d]  = o;
        HX[t * Dm + d] = __float2half_rn(o);
    }
}

// -------- x = target_embed + sinusoid PE (dual write) --------
__global__ void pe_kernel(const float* __restrict__ te,
                          float* __restrict__ x, __half* __restrict__ hx)
{
    int idx = blockIdx.x * 256 + threadIdx.x;
    if (idx >= NTOK * Dm) return;
    int d = idx % Dm;
    int tok = idx / Dm;
    int s = tok % Sq;
    int j = d >> 1;
    float div = expf(-(float)(2 * j) * (logf(10000.f) / (float)Dm));
    float ang = (float)s * div;
    float p = (d & 1) ? cosf(ang) : sinf(ang);
    float o = te[idx] + p;
    x[idx]  = o;
    hx[idx] = __float2half_rn(o);
}

// -------- dec softmax fused: reads x, writes hdec (fp16) + ft ------------
__global__ __launch_bounds__(256) void dec_softmax(
    const float* __restrict__ x, __half* __restrict__ hdec,
    float* __restrict__ ft)
{
    long rr = blockIdx.x;              // 0..NDEC-1
    int b = (int)(rr / (Sq - 1)), s = (int)(rr % (Sq - 1));
    const float* xr = x + ((long)(b * Sq + s)) * Dm;
    int tid = threadIdx.x;
    __shared__ float red[256];
    float v[3];
    float mx = -1e30f;
    #pragma unroll
    for (int i = 0; i < 3; i++) {
        int d = tid + i * 256;
        v[i] = xr[d];
        hdec[rr * Dm + d] = __float2half_rn(v[i]);
        mx = fmaxf(mx, v[i]);
    }
    red[tid] = mx; __syncthreads();
    for (int st = 128; st > 0; st >>= 1) {
        if (tid < st) red[tid] = fmaxf(red[tid], red[tid + st]);
        __syncthreads();
    }
    float m = red[0]; __syncthreads();
    float sum = 0.f;
    #pragma unroll
    for (int i = 0; i < 3; i++) { v[i] = __expf(v[i] - m); sum += v[i]; }
    red[tid] = sum; __syncthreads();
    for (int st = 128; st > 0; st >>= 1) {
        if (tid < st) red[tid] += red[tid + st];
        __syncthreads();
    }
    float inv = 1.f / red[0];
    #pragma unroll
    for (int i = 0; i < 3; i++)
        ft[rr * Dm + tid + i * 256] = v[i] * inv;
}

static inline dim3 gemm_grid(int M, int N, int z = 1) {
    return dim3((N + BN - 1) / BN, (M + BM - 1) / BM, z);
}
static inline int conv_grid(long n) { return (int)((n / 8 + 255) / 256); }

extern "C" void kernel_launch(void* const* d_in, const int* in_sizes, int n_in,
                              void* d_out, int out_size)
{
    const float* fv          = (const float*)d_in[0];
    const float* te          = (const float*)d_in[1];
    const float* self_in_w   = (const float*)d_in[2];
    const float* self_in_b   = (const float*)d_in[3];
    const float* self_out_w  = (const float*)d_in[4];
    const float* self_out_b  = (const float*)d_in[5];
    const float* cross_in_w  = (const float*)d_in[6];
    const float* cross_in_b  = (const float*)d_in[7];
    const float* cross_out_w = (const float*)d_in[8];
    const float* cross_out_b = (const float*)d_in[9];
    const float* lin1_w      = (const float*)d_in[10];
    const float* lin1_b      = (const float*)d_in[11];
    const float* lin2_w      = (const float*)d_in[12];
    const float* lin2_b      = (const float*)d_in[13];
    const float* ln_w        = (const float*)d_in[14];
    const float* ln_b        = (const float*)d_in[15];
    const float* fc_out_w    = (const float*)d_in[16];

    float* out    = (float*)d_out;
    float* logits = out;
    float* ft     = out + (long)NDEC * VOC;

    float *px, *po;
    __half *hx, *hattn, *hff, *hdec, *hfv, *hqkv, *hq, *hkv6;
    __half *hsi, *hso, *hci, *hco, *hl1, *hl2, *hfc;
    cudaGetSymbolAddress((void**)&px,    g_x);
    cudaGetSymbolAddress((void**)&po,    g_o);
    cudaGetSymbolAddress((void**)&hx,    g_hx);
    cudaGetSymbolAddress((void**)&hattn, g_hattn);
    cudaGetSymbolAddress((void**)&hff,   g_hff);
    cudaGetSymbolAddress((void**)&hdec,  g_hdec);
    cudaGetSymbolAddress((void**)&hfv,   g_hfv);
    cudaGetSymbolAddress((void**)&hqkv,  g_hqkv);
    cudaGetSymbolAddress((void**)&hq,    g_hq);
    cudaGetSymbolAddress((void**)&hkv6,  g_hkv6);
    cudaGetSymbolAddress((void**)&hsi,   g_h_si);
    cudaGetSymbolAddress((void**)&hso,   g_h_so);
    cudaGetSymbolAddress((void**)&hci,   g_h_ci);
    cudaGetSymbolAddress((void**)&hco,   g_h_co);
    cudaGetSymbolAddress((void**)&hl1,   g_h_l1);
    cudaGetSymbolAddress((void**)&hl2,   g_h_l2);
    cudaGetSymbolAddress((void**)&hfc,   g_h_fc);

    f2h_kernel<<<conv_grid((long)NL*3*Dm*Dm), 256>>>(self_in_w,  hsi, NL*3*Dm*Dm);
    f2h_kernel<<<conv_grid((long)NL*Dm*Dm),   256>>>(self_out_w, hso, NL*Dm*Dm);
    f2h_kernel<<<conv_grid((long)NL*3*Dm*Dm), 256>>>(cross_in_w, hci, NL*3*Dm*Dm);
    f2h_kernel<<<conv_grid((long)NL*Dm*Dm),   256>>>(cross_out_w,hco, NL*Dm*Dm);
    f2h_kernel<<<conv_grid((long)NL*FFd*Dm),  256>>>(lin1_w,     hl1, NL*FFd*Dm);
    f2h_kernel<<<conv_grid((long)NL*Dm*FFd),  256>>>(lin2_w,     hl2, NL*Dm*FFd);
    f2h_kernel<<<conv_grid((long)VOC*Dm),     256>>>(fc_out_w,   hfc, (int)((long)VOC*Dm));
    f2h_kernel<<<conv_grid((long)NMEM*Dm),    256>>>(fv,         hfv, NMEM*Dm);

    pe_kernel<<<(NTOK * Dm + 255) / 256, 256>>>(te, px, hx);

    // all-layer cross-KV in ONE batched launch (depends only on fv)
    mma_gemm<<<gemm_grid(NMEM, 2 * Dm, NL), 256>>>(
        hfv, hci + (long)Dm * Dm, cross_in_b + Dm, nullptr, hkv6,
        NMEM, 2 * Dm, Dm, 0,
        0L, (long)3 * Dm * Dm, (long)3 * Dm, (long)NMEM * 2 * Dm);

    dim3 agrid(Sq / FTQ, NHh, Bq);

    for (int l = 0; l < NL; l++) {
        const __half* siw = hsi + (long)l * 3 * Dm * Dm;
        const __half* sow = hso + (long)l * Dm * Dm;
        const __half* ciw = hci + (long)l * 3 * Dm * Dm;
        const __half* cow = hco + (long)l * Dm * Dm;
        const __half* l1w = hl1 + (long)l * FFd * Dm;
        const __half* l2w = hl2 + (long)l * Dm * FFd;
        __half* hkv = hkv6 + (long)l * NMEM * 2 * Dm;
        const float* sib = self_in_b  + (long)l * 3 * Dm;
        const float* sob = self_out_b + (long)l * Dm;
        const float* cib = cross_in_b  + (long)l * 3 * Dm;
        const float* cob = cross_out_b + (long)l * Dm;
        const float* l1b = lin1_b + (long)l * FFd;
        const float* l2b = lin2_b + (long)l * Dm;
        const float* lw  = ln_w + (long)l * 3 * Dm;
        const float* lb  = ln_b + (long)l * 3 * Dm;

        // ---- self attention ----
        mma_gemm<<<gemm_grid(NTOK, 3 * Dm), 256>>>(hx, siw, sib, nullptr, hqkv,
                                                   NTOK, 3 * Dm, Dm, 0, 0, 0, 0, 0);
        flash_attn<<<agrid, 128>>>(hqkv, 3 * Dm,
                                   hqkv + Dm, 3 * Dm,
                                   hqkv + 2 * Dm, 3 * Dm,
                                   hattn, Dm, Sq, 1);
        mma_gemm<<<gemm_grid(NTOK, Dm), 256>>>(hattn, sow, sob, po, nullptr,
                                               NTOK, Dm, Dm, 0, 0, 0, 0, 0);
        add_ln_kernel<<<NTOK, 256>>>(px, po, lw, lb, hx);

        // ---- cross attention ----
        mma_gemm<<<gemm_grid(NTOK, Dm), 256>>>(hx, ciw, cib, nullptr, hq,
                                               NTOK, Dm, Dm, 0, 0, 0, 0, 0);
        flash_attn<<<agrid, 128>>>(hq, Dm,
                                   hkv, 2 * Dm,
                                   hkv + Dm, 2 * Dm,
                                   hattn, Dm, NV, 0);
        mma_gemm<<<gemm_grid(NTOK, Dm), 256>>>(hattn, cow, cob, po, nullptr,
                                               NTOK, Dm, Dm, 0, 0, 0, 0, 0);
        add_ln_kernel<<<NTOK, 256>>>(px, po, lw + Dm, lb + Dm, hx);

        // ---- FFN ----
        mma_gemm<<<gemm_grid(NTOK, FFd), 256>>>(hx, l1w, l1b, nullptr, hff,
                                                NTOK, FFd, Dm, 1, 0, 0, 0, 0);
        mma_gemm<<<gemm_grid(NTOK, Dm), 256>>>(hff, l2w, l2b, po, nullptr,
                                               NTOK, Dm, FFd, 0, 0, 0, 0, 0);
        add_ln_kernel<<<NTOK, 256>>>(px, po, lw + 2 * Dm, lb + 2 * Dm, hx);
    }

    dec_softmax<<<NDEC, 256>>>(px, hdec, ft);
    mma_gemm<<<gemm_grid(NDEC, VOC), 256>>>(hdec, hfc, nullptr, logits, nullptr,
                                            NDEC, VOC, Dm, 0, 0, 0, 0, 0);
}